// round 4
// baseline (speedup 1.0000x reference)
#include <cuda_runtime.h>

// Problem constants (fixed by setup_inputs)
constexpr int B = 4, H = 1024, W = 1024;
constexpr int TX = 32;          // tile width
constexpr int TY = 16;          // tile height
constexpr int G  = 8;           // outputs per thread (4 f32x2 pairs, vertical)
constexpr int HX = TX + 10;     // 42 halo cols
constexpr int HY = TY + 10;     // 26 halo rows (even: keeps float2 alignment; 26/2=13 odd: conflict-free)

typedef unsigned long long u64;

__device__ __forceinline__ u64 pk(float lo, float hi) {
    u64 r; asm("mov.b64 %0,{%1,%2};" : "=l"(r) : "f"(lo), "f"(hi)); return r;
}
__device__ __forceinline__ void up(u64 v, float& lo, float& hi) {
    asm("mov.b64 {%0,%1},%2;" : "=f"(lo), "=f"(hi) : "l"(v));
}
__device__ __forceinline__ u64 mul2(u64 a, u64 b) {
    u64 d; asm("mul.rn.f32x2 %0,%1,%2;" : "=l"(d) : "l"(a), "l"(b)); return d;
}
__device__ __forceinline__ u64 add2(u64 a, u64 b) {
    u64 d; asm("add.rn.f32x2 %0,%1,%2;" : "=l"(d) : "l"(a), "l"(b)); return d;
}
__device__ __forceinline__ u64 fma2(u64 a, u64 b, u64 c) {
    u64 d; asm("fma.rn.f32x2 %0,%1,%2,%3;" : "=l"(d) : "l"(a), "l"(b), "l"(c)); return d;
}
__device__ __forceinline__ float rcpa(float x) {
    float r; asm("rcp.approx.f32 %0,%1;" : "=f"(r) : "f"(x)); return r;
}

#define MK 1e30f
// Q[dy+5][dx+5] = dist - 0.5 (disk-mask zeros -> 1e30 so saturatef gives 0).
__device__ constexpr float Q[11][11] = {
  {MK,MK,MK,4.885164807f,4.599019514f,4.5f,4.599019514f,4.885164807f,MK,MK,MK},
  {MK,MK,4.5f,3.972135955f,3.623105626f,3.5f,3.623105626f,3.972135955f,4.5f,MK,MK},
  {MK,4.5f,3.742640687f,3.105551276f,2.662277660f,2.5f,2.662277660f,3.105551276f,3.742640687f,4.5f,MK},
  {4.885164807f,3.972135955f,3.105551276f,2.328427125f,1.736067977f,1.5f,1.736067977f,2.328427125f,3.105551276f,3.972135955f,4.885164807f},
  {4.599019514f,3.623105626f,2.662277660f,1.736067977f,0.914213562f,0.5f,0.914213562f,1.736067977f,2.662277660f,3.623105626f,4.599019514f},
  {4.5f,3.5f,2.5f,1.5f,0.5f,-0.5f,0.5f,1.5f,2.5f,3.5f,4.5f},
  {4.599019514f,3.623105626f,2.662277660f,1.736067977f,0.914213562f,0.5f,0.914213562f,1.736067977f,2.662277660f,3.623105626f,4.599019514f},
  {4.885164807f,3.972135955f,3.105551276f,2.328427125f,1.736067977f,1.5f,1.736067977f,2.328427125f,3.105551276f,3.972135955f,4.885164807f},
  {MK,4.5f,3.742640687f,3.105551276f,2.662277660f,2.5f,2.662277660f,3.105551276f,3.742640687f,4.5f,MK},
  {MK,MK,4.5f,3.972135955f,3.623105626f,3.5f,3.623105626f,3.972135955f,4.5f,MK,MK},
  {MK,MK,MK,4.885164807f,4.599019514f,4.5f,4.599019514f,4.885164807f,MK,MK,MK}
};

// Column-major SoA halo arrays: SM[q][col][row], q = 0..4 base {es,coc,r,g,b},
// q = 5..9 one-row-shifted copies (SM[5+q'][c][r] == SM[q'][c][r+1]) so that a
// (row, row+1) pair is always an aligned LDS.64 regardless of row parity.
__global__ __launch_bounds__(64, 5)
void scatter_render_kernel(const float* __restrict__ x,
                           const float* __restrict__ lens,
                           float* __restrict__ out)
{
    __shared__ __align__(16) float SM[10][HX][HY];

    const int b   = blockIdx.z;
    const int gx0 = blockIdx.x * TX;
    const int gy0 = blockIdx.y * TY;

    const float scale = fabsf(lens[b]);
    const float* __restrict__ xb = x + (size_t)b * 4 * H * W;
    const float* __restrict__ pr = xb;
    const float* __restrict__ pg = xb + H * W;
    const float* __restrict__ pb = xb + 2 * H * W;
    const float* __restrict__ pd = xb + 3 * H * W;

    // ---- halo fill: row-major iteration (coalesced LDG), column-major STS ----
    const int tid = threadIdx.y * TX + threadIdx.x;
    for (int idx = tid; idx < HY * HX; idx += 64) {
        int yy = idx / HX;
        int xx = idx - yy * HX;
        int sy = gy0 + yy - 5; sy = min(max(sy, 0), H - 1);
        int sx = gx0 + xx - 5; sx = min(max(sx, 0), W - 1);
        int o  = sy * W + sx;
        float d  = pd[o];
        float es = __expf(4.0f * d);
        float cc = scale * fabsf(d);
        float rv = pr[o], gv = pg[o], bv = pb[o];
        SM[0][xx][yy] = es; SM[1][xx][yy] = cc;
        SM[2][xx][yy] = rv; SM[3][xx][yy] = gv; SM[4][xx][yy] = bv;
        if (yy > 0) {
            SM[5][xx][yy-1] = es; SM[6][xx][yy-1] = cc;
            SM[7][xx][yy-1] = rv; SM[8][xx][yy-1] = gv; SM[9][xx][yy-1] = bv;
        }
    }
    __syncthreads();

    // ---- main gather ----
    const int tx = threadIdx.x;
    const int ry = G * threadIdx.y;          // 0 or 8 (even)

    // ed[p] = (exp4d at out rows ry+2p, ry+2p+1): rows ry+5+2p (odd base) ->
    // shifted es copy (q=5) at even row ry+4+2p: aligned LDS.64.
    u64 ed[4];
    #pragma unroll
    for (int p = 0; p < 4; ++p)
        ed[p] = *(const u64*)&SM[5][tx + 5][ry + 4 + 2*p];

    u64 aR[4], aG[4], aB[4], aD[4];
    #pragma unroll
    for (int p = 0; p < 4; ++p) { aR[p] = 0; aG[p] = 0; aB[p] = 0; aD[p] = 0; }

    #pragma unroll
    for (int sc = 0; sc < 11; ++sc) {
        const int cc = tx + sc;
        #pragma unroll
        for (int u = 0; u < G + 9; ++u) {    // row-pair vector (ry+u, ry+u+1)
            u64 esv, cocv, rv, gv, bv;
            if (u & 1) {                     // odd base row -> shifted arrays
                const int r = ry + u - 1;
                esv  = *(const u64*)&SM[5][cc][r];
                cocv = *(const u64*)&SM[6][cc][r];
                rv   = *(const u64*)&SM[7][cc][r];
                gv   = *(const u64*)&SM[8][cc][r];
                bv   = *(const u64*)&SM[9][cc][r];
            } else {
                const int r = ry + u;
                esv  = *(const u64*)&SM[0][cc][r];
                cocv = *(const u64*)&SM[1][cc][r];
                rv   = *(const u64*)&SM[2][cc][r];
                gv   = *(const u64*)&SM[3][cc][r];
                bv   = *(const u64*)&SM[4][cc][r];
            }
            float c_lo, c_hi; up(cocv, c_lo, c_hi);

            #pragma unroll
            for (int p = 0; p < 4; ++p) {
                if (u >= 2*p && u <= 2*p + 10) {     // compile-time prune
                    const float c1 = Q[u - 2*p][sc]; // same immediate for both lanes
                    const float w0 = __saturatef(c_lo - c1);
                    const float w1 = __saturatef(c_hi - c1);
                    const u64 wv  = pk(w0, w1);
                    const u64 den = add2(esv, ed[p]);
                    float d0, d1; up(den, d0, d1);
                    const u64 iv  = pk(rcpa(d0), rcpa(d1));
                    const u64 wo  = mul2(mul2(wv, esv), iv);
                    aR[p] = fma2(wo, rv, aR[p]);
                    aG[p] = fma2(wo, gv, aG[p]);
                    aB[p] = fma2(wo, bv, aB[p]);
                    aD[p] = add2(aD[p], wo);
                }
            }
        }
    }

    // ---- epilogue: 8 outputs x 3 channels ----
    const int gx = gx0 + tx;
    float* __restrict__ ob = out + (size_t)b * 3 * H * W;
    #pragma unroll
    for (int p = 0; p < 4; ++p) {
        float r0, r1, g0, g1, b0, b1, d0, d1;
        up(aR[p], r0, r1); up(aG[p], g0, g1);
        up(aB[p], b0, b1); up(aD[p], d0, d1);
        const float i0 = rcpa(d0 + 1e-8f);
        const float i1 = rcpa(d1 + 1e-8f);
        const int gy = gy0 + ry + 2*p;
        const int o0 = gy * W + gx;
        ob[o0]               = r0 * i0;
        ob[o0 + W]           = r1 * i1;
        ob[H*W + o0]         = g0 * i0;
        ob[H*W + o0 + W]     = g1 * i1;
        ob[2*H*W + o0]       = b0 * i0;
        ob[2*H*W + o0 + W]   = b1 * i1;
    }
}

extern "C" void kernel_launch(void* const* d_in, const int* in_sizes, int n_in,
                              void* d_out, int out_size)
{
    const float* x    = (const float*)d_in[0];
    const float* lens = (const float*)d_in[1];
    float* out        = (float*)d_out;

    dim3 block(TX, 2, 1);                   // 64 threads, 8 rows per thread
    dim3 grid(W / TX, H / TY, B);           // 32 x 64 x 4
    scatter_render_kernel<<<grid, block>>>(x, lens, out);
}

// round 5
// speedup vs baseline: 2.0708x; 2.0708x over previous
#include <cuda_runtime.h>

// Problem constants (fixed by setup_inputs)
constexpr int B = 4, H = 1024, W = 1024;
constexpr int TX = 32;          // output tile width
constexpr int TY = 16;          // output tile height (2 rows per thread)
constexpr int HX = TX + 10;     // 42: halo tile width
constexpr int HY = TY + 10;     // 26: halo tile height

typedef unsigned long long u64; // packed f32x2 carrier (even/odd reg pair)

__device__ __forceinline__ u64 pk(float lo, float hi) {
    u64 r; asm("mov.b64 %0,{%1,%2};" : "=l"(r) : "f"(lo), "f"(hi)); return r;
}
__device__ __forceinline__ void up(u64 v, float& lo, float& hi) {
    asm("mov.b64 {%0,%1},%2;" : "=f"(lo), "=f"(hi) : "l"(v));
}
__device__ __forceinline__ u64 fma2(u64 a, u64 b, u64 c) {
    u64 d; asm("fma.rn.f32x2 %0,%1,%2,%3;" : "=l"(d) : "l"(a), "l"(b), "l"(c)); return d;
}
__device__ __forceinline__ float rcpa(float x) {
    float r; asm("rcp.approx.f32 %0,%1;" : "=f"(r) : "f"(x)); return r;
}

#define MK 1e30f
// C1P[k][c]: k=0 and k=12 are OOB pads (weight 0 via 1e30).
// k=1..11 hold (dist - 0.5) for dy = k-6 (offsets -5..5); disk-mask zeros
// replaced by 1e30 so __saturatef(coc - c1) == 0 there.
__device__ constexpr float C1P[13][11] = {
  {MK,MK,MK,MK,MK,MK,MK,MK,MK,MK,MK},
  {MK,MK,MK,4.885164807f,4.599019514f,4.5f,4.599019514f,4.885164807f,MK,MK,MK},
  {MK,MK,4.5f,3.972135955f,3.623105626f,3.5f,3.623105626f,3.972135955f,4.5f,MK,MK},
  {MK,4.5f,3.742640687f,3.105551276f,2.662277660f,2.5f,2.662277660f,3.105551276f,3.742640687f,4.5f,MK},
  {4.885164807f,3.972135955f,3.105551276f,2.328427125f,1.736067977f,1.5f,1.736067977f,2.328427125f,3.105551276f,3.972135955f,4.885164807f},
  {4.599019514f,3.623105626f,2.662277660f,1.736067977f,0.914213562f,0.5f,0.914213562f,1.736067977f,2.662277660f,3.623105626f,4.599019514f},
  {4.5f,3.5f,2.5f,1.5f,0.5f,-0.5f,0.5f,1.5f,2.5f,3.5f,4.5f},
  {4.599019514f,3.623105626f,2.662277660f,1.736067977f,0.914213562f,0.5f,0.914213562f,1.736067977f,2.662277660f,3.623105626f,4.599019514f},
  {4.885164807f,3.972135955f,3.105551276f,2.328427125f,1.736067977f,1.5f,1.736067977f,2.328427125f,3.105551276f,3.972135955f,4.885164807f},
  {MK,4.5f,3.742640687f,3.105551276f,2.662277660f,2.5f,2.662277660f,3.105551276f,3.742640687f,4.5f,MK},
  {MK,MK,4.5f,3.972135955f,3.623105626f,3.5f,3.623105626f,3.972135955f,4.5f,MK,MK},
  {MK,MK,MK,4.885164807f,4.599019514f,4.5f,4.599019514f,4.885164807f,MK,MK,MK},
  {MK,MK,MK,MK,MK,MK,MK,MK,MK,MK,MK}
};

__global__ __launch_bounds__(256, 6)
void scatter_render_kernel(const float* __restrict__ x,
                           const float* __restrict__ lens,
                           float* __restrict__ out)
{
    __shared__ __align__(16) float4 s_f4[HY][HX];  // (r, g, b, 1.0)
    __shared__ __align__(8)  float2 s_f2[HY][HX];  // (inv_es = e^{-4 disp}, coc)

    const int b   = blockIdx.z;
    const int gx0 = blockIdx.x * TX;
    const int gy0 = blockIdx.y * TY;

    const float scale = fabsf(lens[b]);
    const float* __restrict__ xb = x + (size_t)b * 4 * H * W;
    const float* __restrict__ pr = xb;
    const float* __restrict__ pg = xb + H * W;
    const float* __restrict__ pb = xb + 2 * H * W;
    const float* __restrict__ pd = xb + 3 * H * W;

    // ---- cooperative halo-tile fill (with edge clamp) ----
    const int tid = threadIdx.y * TX + threadIdx.x;
    for (int idx = tid; idx < HY * HX; idx += 256) {
        int yy = idx / HX;
        int xx = idx - yy * HX;
        int sy = gy0 + yy - 5; sy = min(max(sy, 0), H - 1);
        int sx = gx0 + xx - 5; sx = min(max(sx, 0), W - 1);
        int o  = sy * W + sx;
        float d  = pd[o];
        float ie = __expf(-4.0f * d);       // e^{-4 disp}
        float cc = scale * fabsf(d);
        s_f2[yy][xx] = make_float2(ie, cc);
        s_f4[yy][xx] = make_float4(pr[o], pg[o], pb[o], 1.0f);
    }
    __syncthreads();

    // ---- main gather: each thread owns 2 vertically adjacent outputs ----
    const int tx = threadIdx.x;
    const int ry = 2 * threadIdx.y;

    // ed = e^{+4 disp_dst} = rcp(inv_es at dst)
    const float ed0 = rcpa(s_f2[ry + 5][tx + 5].x);
    const float ed1 = rcpa(s_f2[ry + 6][tx + 5].x);

    u64 aRG0 = 0, aB1_0 = 0;   // (num_r, num_g), (num_b, den) for out0
    u64 aRG1 = 0, aB1_1 = 0;   // ... for out1

    #pragma unroll
    for (int sr = 0; sr < 12; ++sr) {       // union of both outputs' 11 rows
        #pragma unroll
        for (int sc = 0; sc < 11; ++sc) {
            const float2 f2 = s_f2[ry + sr][tx + sc];   // (inv_es, coc)
            const float4 f4 = s_f4[ry + sr][tx + sc];   // (r, g, b, 1)
            const u64 rg = pk(f4.x, f4.y);              // aligned halves of the
            const u64 b1 = pk(f4.z, f4.w);              // LDS.128 quad (free)

            // out0: dy = sr - 5 -> c1 row sr+1 ; out1: dy = sr - 6 -> row sr
            const float w0 = __saturatef(f2.y - C1P[sr + 1][sc]);
            const float w1 = __saturatef(f2.y - C1P[sr    ][sc]);
            const float o0 = rcpa(fmaf(ed0, f2.x, 1.0f));  // sigmoid gate
            const float o1 = rcpa(fmaf(ed1, f2.x, 1.0f));
            const float wo0 = w0 * o0;
            const float wo1 = w1 * o1;
            const u64 w02 = pk(wo0, wo0);
            const u64 w12 = pk(wo1, wo1);
            aRG0  = fma2(w02, rg, aRG0);
            aB1_0 = fma2(w02, b1, aB1_0);
            aRG1  = fma2(w12, rg, aRG1);
            aB1_1 = fma2(w12, b1, aB1_1);
        }
    }

    // ---- epilogue: normalize and store 2 outputs x 3 channels ----
    float r0, g0, b0, d0, r1, g1, b1v, d1;
    up(aRG0, r0, g0); up(aB1_0, b0, d0);
    up(aRG1, r1, g1); up(aB1_1, b1v, d1);

    const float i0 = rcpa(d0 + 1e-8f);
    const float i1 = rcpa(d1 + 1e-8f);

    const int gx = gx0 + tx;
    const int gy = gy0 + ry;
    float* __restrict__ ob = out + (size_t)b * 3 * H * W;
    const int o0 = gy * W + gx;
    const int o1 = o0 + W;
    ob[o0]             = r0 * i0;
    ob[H * W + o0]     = g0 * i0;
    ob[2 * H * W + o0] = b0 * i0;
    ob[o1]             = r1 * i1;
    ob[H * W + o1]     = g1 * i1;
    ob[2 * H * W + o1] = b1v * i1;
}

extern "C" void kernel_launch(void* const* d_in, const int* in_sizes, int n_in,
                              void* d_out, int out_size)
{
    const float* x    = (const float*)d_in[0];
    const float* lens = (const float*)d_in[1];
    float* out        = (float*)d_out;

    dim3 block(TX, TY / 2, 1);              // 32 x 8 = 256 threads
    dim3 grid(W / TX, H / TY, B);           // 32 x 64 x 4
    scatter_render_kernel<<<grid, block>>>(x, lens, out);
}